// round 11
// baseline (speedup 1.0000x reference)
#include <cuda_runtime.h>
#include <cuda_bf16.h>
#include <cstdint>

#define BATCH 2048
#define SEQ   512
#define TM    128
#define NTILE 4
#define PW    104   // bf16 pitch (208B rows -> conflict-free ldmatrix)

// ---- SMEM layout (bytes) ----
#define OFF_C    0                      // c[96] f32
#define OFF_P    384                    // P[96] f32
#define OFF_Z    768
#define OFF_M    772
#define OFF_F    776
#define OFF_R    800                    // 4 f32 warp-reduce scratch
#define OFF_S    816                    // scores[128] f32
#define OFF_WT   1328                   // weights/tgt staging [128] f32
#define OFF_WHI  1840                   // Whi 96xPW bf16 = 19968
#define OFF_WLO  (OFF_WHI + 19968)      // 21808
#define OFF_AHI  (OFF_WLO + 19968)      // 41776, Ahi 128xPW bf16 = 26624
#define OFF_ALO  (OFF_AHI + 26624)      // 68400
#define SMEM_TOTAL (OFF_ALO + 26624)    // 95024

__device__ __forceinline__ uint32_t smem_u32(const void* p) {
    uint32_t a;
    asm("{ .reg .u64 t; cvta.to.shared.u64 t, %1; cvt.u32.u64 %0, t; }" : "=r"(a) : "l"(p));
    return a;
}
__device__ __forceinline__ void ldsm4(uint32_t* r, uint32_t addr) {
    asm volatile("ldmatrix.sync.aligned.m8n8.x4.shared.b16 {%0,%1,%2,%3}, [%4];"
        : "=r"(r[0]), "=r"(r[1]), "=r"(r[2]), "=r"(r[3]) : "r"(addr));
}
__device__ __forceinline__ void mma_bf16(float* c, const uint32_t* a, uint32_t b0, uint32_t b1) {
    asm volatile("mma.sync.aligned.m16n8k16.row.col.f32.bf16.bf16.f32 "
        "{%0,%1,%2,%3}, {%4,%5,%6,%7}, {%8,%9}, {%0,%1,%2,%3};"
        : "+f"(c[0]), "+f"(c[1]), "+f"(c[2]), "+f"(c[3])
        : "r"(a[0]), "r"(a[1]), "r"(a[2]), "r"(a[3]), "r"(b0), "r"(b1));
}
__device__ __forceinline__ uint32_t pack_bf16x2(float lo, float hi) {
    uint32_t r;
    asm("cvt.rn.satfinite.bf16x2.f32 %0, %1, %2;" : "=r"(r) : "f"(hi), "f"(lo));
    return r;
}
__device__ __forceinline__ float sigf(float z) {
    return 1.0f / (1.0f + __expf(-z));
}

__global__ void __launch_bounds__(128) attn_kernel(
    const float* __restrict__ seq, const float* __restrict__ tgt,
    const int* __restrict__ mask,
    const float* __restrict__ w1, const float* __restrict__ b1,
    const float* __restrict__ w2, const float* __restrict__ b2,
    float* __restrict__ out)
{
    extern __shared__ __align__(16) char smem[];
    const uint32_t sb = smem_u32(smem);
    const int b = blockIdx.x, tid = threadIdx.x, wid = tid >> 5, lid = tid & 31;
    const int tig = lid & 3, g = lid >> 2;

    float* sC = (float*)(smem + OFF_C);
    float* sP = (float*)(smem + OFF_P);
    float* sZ = (float*)(smem + OFF_Z);
    float* sM = (float*)(smem + OFF_M);
    float* sF = (float*)(smem + OFF_F);
    float* sR = (float*)(smem + OFF_R);
    float* sS = (float*)(smem + OFF_S);
    float* sW = (float*)(smem + OFF_WT);
    __nv_bfloat16* Whi = (__nv_bfloat16*)(smem + OFF_WHI);
    __nv_bfloat16* Wlo = (__nv_bfloat16*)(smem + OFF_WLO);
    __nv_bfloat16* Ahi = (__nv_bfloat16*)(smem + OFF_AHI);
    __nv_bfloat16* Alo = (__nv_bfloat16*)(smem + OFF_ALO);
    float* fstage = (float*)(smem + OFF_AHI);   // fp32 staging, pitch 97 (96x97x4 = 37KB)

    // ---- build Whi/Wlo (row-major [e][d], pitch PW) + stage w2/tgt ----
    for (int i = tid; i < 96 * 96; i += 128) {
        int e = i / 96, d = i - e * 96;
        float w = __ldg(w1 + i);
        __nv_bfloat16 h = __float2bfloat16(w);
        Whi[e * PW + d] = h;
        Wlo[e * PW + d] = __float2bfloat16(w - __bfloat162float(h));
    }
    for (int i = tid; i < 96 * 96; i += 128) {
        int r = i / 96, c = i - r * 96;
        fstage[r * 97 + c] = __ldg(w2 + i);
    }
    if (tid < 96) sW[tid] = __ldg(tgt + (size_t)b * 96 + tid);
    if (tid < 96) sP[tid] = 0.0f;
    if (tid == 0) { *sZ = 0.0f; *sM = -3.0e38f; }
    __syncthreads();

    // c[e] = b1[e] + b2[e] + tgt . w2[e,:]  (exact fp32)
    if (tid < 96) {
        float acc = __ldg(b1 + tid) + __ldg(b2 + tid);
        const float* wr = fstage + tid * 97;
        #pragma unroll 8
        for (int d = 0; d < 96; ++d) acc = fmaf(sW[d], wr[d], acc);
        sC[tid] = acc;
    }
    __syncthreads();

    // preload per-lane column biases (24 of 96 cols per lane)
    float cc[12][2];
    #pragma unroll
    for (int nt = 0; nt < 12; ++nt) {
        cc[nt][0] = sC[nt * 8 + tig * 2];
        cc[nt][1] = sC[nt * 8 + tig * 2 + 1];
    }

    // per-lane ldmatrix addresses
    const int m0 = wid * 32;
    const int rowA = m0 + ((lid & 8) ? 8 : 0) + (lid & 7);
    const int colA = (lid & 16) ? 8 : 0;
    const uint32_t aAhi = sb + OFF_AHI + (uint32_t)(rowA * PW + colA) * 2u;
    const uint32_t aAlo = sb + OFF_ALO + (uint32_t)(rowA * PW + colA) * 2u;
    const int eB = ((lid & 16) ? 8 : 0) + (lid & 7);
    const int dB = (lid & 8) ? 8 : 0;
    const uint32_t aWhi = sb + OFF_WHI + (uint32_t)(eB * PW + dB) * 2u;
    const uint32_t aWlo = sb + OFF_WLO + (uint32_t)(eB * PW + dB) * 2u;

    const size_t mrow = (size_t)b * (SEQ + 1);

    for (int t = 0; t < NTILE; ++t) {
        // ---- 1. load X tile, split hi/lo, store bf16 planes ----
        const float4* g4 = (const float4*)(seq + ((size_t)b * SEQ + (size_t)t * TM) * 96);
        #pragma unroll 6
        for (int i = tid; i < 3072; i += 128) {
            float4 v = g4[i];
            int e4 = i * 4;
            int r = e4 / 96, c = e4 - r * 96;
            uint32_t h01 = pack_bf16x2(v.x, v.y);
            uint32_t h23 = pack_bf16x2(v.z, v.w);
            float hx = __uint_as_float(h01 << 16), hy = __uint_as_float(h01 & 0xffff0000u);
            float hz = __uint_as_float(h23 << 16), hw = __uint_as_float(h23 & 0xffff0000u);
            uint32_t l01 = pack_bf16x2(v.x - hx, v.y - hy);
            uint32_t l23 = pack_bf16x2(v.z - hz, v.w - hw);
            uint32_t off = (uint32_t)(r * PW + c) * 2u;
            *(uint2*)(smem + OFF_AHI + off) = make_uint2(h01, h23);
            *(uint2*)(smem + OFF_ALO + off) = make_uint2(l01, l23);
        }
        __syncthreads();

        // ---- 2. HMMA: D = Ahi*Whi + Alo*Whi + Ahi*Wlo ----
        float acc[2][12][4];
        #pragma unroll
        for (int mt = 0; mt < 2; ++mt)
            #pragma unroll
            for (int nt = 0; nt < 12; ++nt)
                #pragma unroll
                for (int q = 0; q < 4; ++q) acc[mt][nt][q] = 0.0f;

        for (int ks = 0; ks < 6; ++ks) {
            const uint32_t kb = (uint32_t)ks * 32u;   // 16 bf16 cols
            uint32_t ah[2][4], al[2][4], bb[6][4];
            ldsm4(ah[0], aAhi + kb);
            ldsm4(ah[1], aAhi + 16u * PW * 2u + kb);
            ldsm4(al[0], aAlo + kb);
            ldsm4(al[1], aAlo + 16u * PW * 2u + kb);
            #pragma unroll
            for (int i = 0; i < 6; ++i) ldsm4(bb[i], aWhi + (uint32_t)i * (16u * PW * 2u) + kb);
            #pragma unroll
            for (int mt = 0; mt < 2; ++mt)
                #pragma unroll
                for (int nt = 0; nt < 12; ++nt) {
                    const uint32_t* bp = bb[nt >> 1] + (nt & 1) * 2;
                    mma_bf16(acc[mt][nt], ah[mt], bp[0], bp[1]);
                }
            #pragma unroll
            for (int mt = 0; mt < 2; ++mt)
                #pragma unroll
                for (int nt = 0; nt < 12; ++nt) {
                    const uint32_t* bp = bb[nt >> 1] + (nt & 1) * 2;
                    mma_bf16(acc[mt][nt], al[mt], bp[0], bp[1]);
                }
            #pragma unroll
            for (int i = 0; i < 6; ++i) ldsm4(bb[i], aWlo + (uint32_t)i * (16u * PW * 2u) + kb);
            #pragma unroll
            for (int mt = 0; mt < 2; ++mt)
                #pragma unroll
                for (int nt = 0; nt < 12; ++nt) {
                    const uint32_t* bp = bb[nt >> 1] + (nt & 1) * 2;
                    mma_bf16(acc[mt][nt], ah[mt], bp[0], bp[1]);
                }
        }

        // ---- 3. sigmoid-sum -> row scores ----
        #pragma unroll
        for (int mt = 0; mt < 2; ++mt) {
            float slo = 0.0f, shi = 0.0f;
            #pragma unroll
            for (int nt = 0; nt < 12; ++nt) {
                slo += sigf(acc[mt][nt][0] + cc[nt][0]);
                slo += sigf(acc[mt][nt][1] + cc[nt][1]);
                shi += sigf(acc[mt][nt][2] + cc[nt][0]);
                shi += sigf(acc[mt][nt][3] + cc[nt][1]);
            }
            slo += __shfl_xor_sync(0xffffffffu, slo, 1);
            slo += __shfl_xor_sync(0xffffffffu, slo, 2);
            shi += __shfl_xor_sync(0xffffffffu, shi, 1);
            shi += __shfl_xor_sync(0xffffffffu, shi, 2);
            if (tig == 0) {
                sS[m0 + mt * 16 + g]     = slo;
                sS[m0 + mt * 16 + 8 + g] = shi;
            }
        }
        __syncthreads();

        // ---- 4. online softmax (row per thread) ----
        int mk = __ldg(mask + mrow + (size_t)t * TM + tid);   // bool -> int32
        float score = mk ? -1.0e9f : sS[tid];
        {
            float wmax = score;
            #pragma unroll
            for (int o = 16; o > 0; o >>= 1)
                wmax = fmaxf(wmax, __shfl_xor_sync(0xffffffffu, wmax, o));
            if (lid == 0) sR[wid] = wmax;
        }
        __syncthreads();
        if (tid == 0) {
            float tmax = fmaxf(fmaxf(sR[0], sR[1]), fmaxf(sR[2], sR[3]));
            float newM = fmaxf(*sM, tmax);
            *sF = __expf(*sM - newM);
            *sM = newM;
        }
        __syncthreads();
        float wgt = __expf(score - *sM);
        sW[tid] = wgt;
        {
            float ws = wgt;
            #pragma unroll
            for (int o = 16; o > 0; o >>= 1)
                ws += __shfl_xor_sync(0xffffffffu, ws, o);
            if (lid == 0) sR[wid] = ws;
        }
        __syncthreads();
        if (tid == 0) *sZ = (*sZ) * (*sF) + (sR[0] + sR[1] + sR[2] + sR[3]);

        // ---- 5. weighted pooling of X (hi+lo ~ exact) ----
        if (tid < 96) {
            float F = *sF;
            float pacc = 0.0f;
            const __nv_bfloat16* xh = Ahi + tid;
            const __nv_bfloat16* xl = Alo + tid;
            #pragma unroll 4
            for (int s = 0; s < TM; ++s)
                pacc = fmaf(sW[s], __bfloat162float(xh[s * PW]) + __bfloat162float(xl[s * PW]), pacc);
            sP[tid] = sP[tid] * F + pacc;
        }
        __syncthreads();
    }

    // ---- epilogue: out[e] = b1[e] + (P/Z) . w1[e,:] (exact fp32) ----
    for (int i = tid; i < 96 * 96; i += 128) {
        int r = i / 96, c = i - r * 96;
        fstage[r * 97 + c] = __ldg(w1 + i);
    }
    __syncthreads();
    if (tid < 96) {
        float invZ = 1.0f / (*sZ);
        float acc = __ldg(b1 + tid);
        const float* wr = fstage + tid * 97;
        #pragma unroll 8
        for (int d = 0; d < 96; ++d) acc = fmaf(sP[d] * invZ, wr[d], acc);
        out[(size_t)b * 96 + tid] = acc;
    }
}

extern "C" void kernel_launch(void* const* d_in, const int* in_sizes, int n_in,
                              void* d_out, int out_size) {
    const float* seq = (const float*)d_in[0];
    const float* tgt = (const float*)d_in[1];
    const int* mask = (const int*)d_in[2];
    const float* w1 = (const float*)d_in[3];
    const float* b1 = (const float*)d_in[4];
    const float* w2 = (const float*)d_in[5];
    const float* b2 = (const float*)d_in[6];
    float* out = (float*)d_out;
    (void)in_sizes; (void)n_in; (void)out_size;

    cudaFuncSetAttribute(attn_kernel, cudaFuncAttributeMaxDynamicSharedMemorySize, SMEM_TOTAL);
    attn_kernel<<<BATCH, 128, SMEM_TOTAL>>>(seq, tgt, mask, w1, b1, w2, b2, out);
}

// round 12
// speedup vs baseline: 1.8692x; 1.8692x over previous
#include <cuda_runtime.h>
#include <cuda_bf16.h>
#include <cstdint>

#define BATCH 2048
#define SEQ   512
#define TM    128
#define NTILE 4
#define NTHR  256
#define PW    104   // bf16 pitch (208B rows -> conflict-free ldmatrix)

// ---- SMEM layout (bytes) ----
#define OFF_C    0                      // c[96] f32
#define OFF_P    384                    // P[96] f32
#define OFF_Z    768
#define OFF_M    772
#define OFF_F    776
#define OFF_R    800                    // 4 f32 warp-reduce scratch (warps 0-3)
#define OFF_S    816                    // scores[128] f32
#define OFF_WT   1328                   // softmax weights [128] f32
#define OFF_PAR  1840                   // pooling partials [192] f32
#define OFF_WHI  2608                   // Whi 96xPW bf16 = 19968
#define OFF_WLO  (OFF_WHI + 19968)
#define OFF_AHI  (OFF_WLO + 19968)      // Ahi 128xPW bf16 = 26624
#define OFF_ALO  (OFF_AHI + 26624)
#define SMEM_TOTAL (OFF_ALO + 26624)    // 95792

__device__ __forceinline__ uint32_t smem_u32(const void* p) {
    uint32_t a;
    asm("{ .reg .u64 t; cvta.to.shared.u64 t, %1; cvt.u32.u64 %0, t; }" : "=r"(a) : "l"(p));
    return a;
}
__device__ __forceinline__ void ldsm4(uint32_t* r, uint32_t addr) {
    asm volatile("ldmatrix.sync.aligned.m8n8.x4.shared.b16 {%0,%1,%2,%3}, [%4];"
        : "=r"(r[0]), "=r"(r[1]), "=r"(r[2]), "=r"(r[3]) : "r"(addr));
}
__device__ __forceinline__ void mma_bf16(float* c, const uint32_t* a, uint32_t b0, uint32_t b1) {
    asm volatile("mma.sync.aligned.m16n8k16.row.col.f32.bf16.bf16.f32 "
        "{%0,%1,%2,%3}, {%4,%5,%6,%7}, {%8,%9}, {%0,%1,%2,%3};"
        : "+f"(c[0]), "+f"(c[1]), "+f"(c[2]), "+f"(c[3])
        : "r"(a[0]), "r"(a[1]), "r"(a[2]), "r"(a[3]), "r"(b0), "r"(b1));
}
__device__ __forceinline__ uint32_t pack_bf16x2(float lo, float hi) {
    uint32_t r;
    asm("cvt.rn.satfinite.bf16x2.f32 %0, %1, %2;" : "=r"(r) : "f"(hi), "f"(lo));
    return r;
}
__device__ __forceinline__ float sigf(float z) {
    return __fdividef(1.0f, 1.0f + __expf(-z));
}

__global__ void __launch_bounds__(NTHR, 2) attn_kernel(
    const float* __restrict__ seq, const float* __restrict__ tgt,
    const int* __restrict__ mask,
    const float* __restrict__ w1, const float* __restrict__ b1,
    const float* __restrict__ w2, const float* __restrict__ b2,
    float* __restrict__ out)
{
    extern __shared__ __align__(16) char smem[];
    const uint32_t sb = smem_u32(smem);
    const int b = blockIdx.x, tid = threadIdx.x, wid = tid >> 5, lid = tid & 31;
    const int tig = lid & 3, g = lid >> 2;

    float* sC = (float*)(smem + OFF_C);
    float* sP = (float*)(smem + OFF_P);
    float* sZ = (float*)(smem + OFF_Z);
    float* sM = (float*)(smem + OFF_M);
    float* sF = (float*)(smem + OFF_F);
    float* sR = (float*)(smem + OFF_R);
    float* sS = (float*)(smem + OFF_S);
    float* sW = (float*)(smem + OFF_WT);
    float* sPar = (float*)(smem + OFF_PAR);
    __nv_bfloat16* Whi = (__nv_bfloat16*)(smem + OFF_WHI);
    __nv_bfloat16* Wlo = (__nv_bfloat16*)(smem + OFF_WLO);
    __nv_bfloat16* Ahi = (__nv_bfloat16*)(smem + OFF_AHI);
    __nv_bfloat16* Alo = (__nv_bfloat16*)(smem + OFF_ALO);
    float* fstage = (float*)(smem + OFF_AHI);   // fp32 staging, pitch 97 (fits in planes)

    // ---- build Whi/Wlo + stage w2/tgt ----
    for (int i = tid; i < 96 * 96; i += NTHR) {
        int e = i / 96, d = i - e * 96;
        float w = __ldg(w1 + i);
        __nv_bfloat16 h = __float2bfloat16(w);
        Whi[e * PW + d] = h;
        Wlo[e * PW + d] = __float2bfloat16(w - __bfloat162float(h));
    }
    for (int i = tid; i < 96 * 96; i += NTHR) {
        int r = i / 96, c = i - r * 96;
        fstage[r * 97 + c] = __ldg(w2 + i);
    }
    if (tid >= 128 && tid < 224) sW[tid - 128] = __ldg(tgt + (size_t)b * 96 + (tid - 128));
    if (tid < 96) sP[tid] = 0.0f;
    if (tid == 0) { *sZ = 0.0f; *sM = -3.0e38f; }
    __syncthreads();

    // c[e] = b1[e] + b2[e] + tgt . w2[e,:]  (exact fp32)
    if (tid < 96) {
        float acc = __ldg(b1 + tid) + __ldg(b2 + tid);
        const float* wr = fstage + tid * 97;
        #pragma unroll 8
        for (int d = 0; d < 96; ++d) acc = fmaf(sW[d], wr[d], acc);
        sC[tid] = acc;
    }
    __syncthreads();

    // per-lane ldmatrix addresses: warp owns rows [wid*16, wid*16+16)
    const int m0 = wid * 16;
    const int rowA = m0 + (lid & 15);
    const int colA = (lid & 16) ? 8 : 0;
    const uint32_t aAhi = sb + OFF_AHI + (uint32_t)(rowA * PW + colA) * 2u;
    const uint32_t aAlo = sb + OFF_ALO + (uint32_t)(rowA * PW + colA) * 2u;
    const int eB = ((lid & 16) ? 8 : 0) + (lid & 7);
    const int dB = (lid & 8) ? 8 : 0;
    const uint32_t aWhi = sb + OFF_WHI + (uint32_t)(eB * PW + dB) * 2u;
    const uint32_t aWlo = sb + OFF_WLO + (uint32_t)(eB * PW + dB) * 2u;

    const size_t mrow = (size_t)b * (SEQ + 1);

    for (int t = 0; t < NTILE; ++t) {
        // ---- 1. load X tile, split hi/lo, store bf16 planes ----
        const float4* g4 = (const float4*)(seq + ((size_t)b * SEQ + (size_t)t * TM) * 96);
        #pragma unroll 12
        for (int i = tid; i < 3072; i += NTHR) {
            float4 v = g4[i];
            int e4 = i * 4;
            int r = e4 / 96, c = e4 - r * 96;
            uint32_t h01 = pack_bf16x2(v.x, v.y);
            uint32_t h23 = pack_bf16x2(v.z, v.w);
            float hx = __uint_as_float(h01 << 16), hy = __uint_as_float(h01 & 0xffff0000u);
            float hz = __uint_as_float(h23 << 16), hw = __uint_as_float(h23 & 0xffff0000u);
            uint32_t l01 = pack_bf16x2(v.x - hx, v.y - hy);
            uint32_t l23 = pack_bf16x2(v.z - hz, v.w - hw);
            uint32_t off = (uint32_t)(r * PW + c) * 2u;
            *(uint2*)(smem + OFF_AHI + off) = make_uint2(h01, h23);
            *(uint2*)(smem + OFF_ALO + off) = make_uint2(l01, l23);
        }
        __syncthreads();

        // ---- 2. HMMA: D = Ahi*Whi + Alo*Whi + Ahi*Wlo (16 rows per warp) ----
        float acc[12][4];
        #pragma unroll
        for (int nt = 0; nt < 12; ++nt)
            #pragma unroll
            for (int q = 0; q < 4; ++q) acc[nt][q] = 0.0f;

        for (int ks = 0; ks < 6; ++ks) {
            const uint32_t kb = (uint32_t)ks * 32u;
            uint32_t ah[4], al[4], bb[6][4];
            ldsm4(ah, aAhi + kb);
            ldsm4(al, aAlo + kb);
            #pragma unroll
            for (int i = 0; i < 6; ++i) ldsm4(bb[i], aWhi + (uint32_t)i * (16u * PW * 2u) + kb);
            #pragma unroll
            for (int nt = 0; nt < 12; ++nt) {
                const uint32_t* bp = bb[nt >> 1] + (nt & 1) * 2;
                mma_bf16(acc[nt], ah, bp[0], bp[1]);
            }
            #pragma unroll
            for (int nt = 0; nt < 12; ++nt) {
                const uint32_t* bp = bb[nt >> 1] + (nt & 1) * 2;
                mma_bf16(acc[nt], al, bp[0], bp[1]);
            }
            #pragma unroll
            for (int i = 0; i < 6; ++i) ldsm4(bb[i], aWlo + (uint32_t)i * (16u * PW * 2u) + kb);
            #pragma unroll
            for (int nt = 0; nt < 12; ++nt) {
                const uint32_t* bp = bb[nt >> 1] + (nt & 1) * 2;
                mma_bf16(acc[nt], ah, bp[0], bp[1]);
            }
        }

        // ---- 3. sigmoid-sum -> row scores ----
        {
            float slo = 0.0f, shi = 0.0f;
            #pragma unroll
            for (int nt = 0; nt < 12; ++nt) {
                float c0 = sC[nt * 8 + tig * 2];
                float c1 = sC[nt * 8 + tig * 2 + 1];
                slo += sigf(acc[nt][0] + c0);
                slo += sigf(acc[nt][1] + c1);
                shi += sigf(acc[nt][2] + c0);
                shi += sigf(acc[nt][3] + c1);
            }
            slo += __shfl_xor_sync(0xffffffffu, slo, 1);
            slo += __shfl_xor_sync(0xffffffffu, slo, 2);
            shi += __shfl_xor_sync(0xffffffffu, shi, 1);
            shi += __shfl_xor_sync(0xffffffffu, shi, 2);
            if (tig == 0) {
                sS[m0 + g]     = slo;
                sS[m0 + 8 + g] = shi;
            }
        }
        __syncthreads();

        // ---- 4. online softmax (rows on warps 0-3) ----
        float score = 0.0f;
        if (tid < 128) {
            int mk = __ldg(mask + mrow + (size_t)t * TM + tid);
            score = mk ? -1.0e9f : sS[tid];
            float wmax = score;
            #pragma unroll
            for (int o = 16; o > 0; o >>= 1)
                wmax = fmaxf(wmax, __shfl_xor_sync(0xffffffffu, wmax, o));
            if (lid == 0) sR[wid] = wmax;
        }
        __syncthreads();
        if (tid == 0) {
            float tmax = fmaxf(fmaxf(sR[0], sR[1]), fmaxf(sR[2], sR[3]));
            float newM = fmaxf(*sM, tmax);
            *sF = __expf(*sM - newM);
            *sM = newM;
        }
        __syncthreads();
        if (tid < 128) {
            float wgt = __expf(score - *sM);
            sW[tid] = wgt;
            #pragma unroll
            for (int o = 16; o > 0; o >>= 1)
                wgt += __shfl_xor_sync(0xffffffffu, wgt, o);
            if (lid == 0) sR[wid] = wgt;
        }
        __syncthreads();
        if (tid == 0) *sZ = (*sZ) * (*sF) + (sR[0] + sR[1] + sR[2] + sR[3]);

        // ---- 5. weighted pooling of X (192 threads: 96 cols x 2 s-halves) ----
        if (tid < 192) {
            int col = (tid < 96) ? tid : tid - 96;
            int s0 = (tid < 96) ? 0 : 64;
            float pacc = 0.0f;
            const __nv_bfloat16* xh = Ahi + col + s0 * PW;
            const __nv_bfloat16* xl = Alo + col + s0 * PW;
            const float* wp = sW + s0;
            #pragma unroll 4
            for (int s = 0; s < 64; ++s)
                pacc = fmaf(wp[s], __bfloat162float(xh[s * PW]) + __bfloat162float(xl[s * PW]), pacc);
            sPar[tid] = pacc;
        }
        __syncthreads();
        if (tid < 96) sP[tid] = sP[tid] * (*sF) + sPar[tid] + sPar[tid + 96];
        __syncthreads();
    }

    // ---- epilogue: out[e] = b1[e] + (P/Z) . w1[e,:] (exact fp32) ----
    for (int i = tid; i < 96 * 96; i += NTHR) {
        int r = i / 96, c = i - r * 96;
        fstage[r * 97 + c] = __ldg(w1 + i);
    }
    __syncthreads();
    if (tid < 96) {
        float invZ = __fdividef(1.0f, *sZ);
        float acc = __ldg(b1 + tid);
        const float* wr = fstage + tid * 97;
        #pragma unroll 8
        for (int d = 0; d < 96; ++d) acc = fmaf(sP[d] * invZ, wr[d], acc);
        out[(size_t)b * 96 + tid] = acc;
    }
}

extern "C" void kernel_launch(void* const* d_in, const int* in_sizes, int n_in,
                              void* d_out, int out_size) {
    const float* seq = (const float*)d_in[0];
    const float* tgt = (const float*)d_in[1];
    const int* mask = (const int*)d_in[2];
    const float* w1 = (const float*)d_in[3];
    const float* b1 = (const float*)d_in[4];
    const float* w2 = (const float*)d_in[5];
    const float* b2 = (const float*)d_in[6];
    float* out = (float*)d_out;
    (void)in_sizes; (void)n_in; (void)out_size;

    cudaFuncSetAttribute(attn_kernel, cudaFuncAttributeMaxDynamicSharedMemorySize, SMEM_TOTAL);
    attn_kernel<<<BATCH, NTHR, SMEM_TOTAL>>>(seq, tgt, mask, w1, b1, w2, b2, out);
}

// round 14
// speedup vs baseline: 2.1085x; 1.1281x over previous
#include <cuda_runtime.h>
#include <cuda_fp16.h>
#include <cstdint>

#define BATCH 2048
#define SEQ   512
#define TM    128
#define NTILE 4
#define NTHR  256
#define PW    104   // fp16 pitch (208B rows -> conflict-free ldmatrix)

// ---- SMEM layout (bytes) ----
#define OFF_C    0                      // c[96] f32
#define OFF_P    384                    // P[96] f32
#define OFF_Z    768
#define OFF_M    772
#define OFF_F    776
#define OFF_R    800                    // 4 f32 warp-reduce scratch
#define OFF_S    816                    // scores[128] f32
#define OFF_WT   1328                   // softmax weights [128] f32
#define OFF_PAR  1840                   // pooling partials [192] f32
#define OFF_WH   2608                   // Wh 96xPW fp16 = 19968
#define OFF_AHI  (OFF_WH + 19968)       // 22576, Ahi 128xPW fp16 = 26624
#define OFF_ALO  (OFF_AHI + 26624)      // 49200
#define SMEM_TOTAL (OFF_ALO + 26624)    // 75824

__device__ __forceinline__ uint32_t smem_u32(const void* p) {
    uint32_t a;
    asm("{ .reg .u64 t; cvta.to.shared.u64 t, %1; cvt.u32.u64 %0, t; }" : "=r"(a) : "l"(p));
    return a;
}
__device__ __forceinline__ void ldsm4(uint32_t* r, uint32_t addr) {
    asm volatile("ldmatrix.sync.aligned.m8n8.x4.shared.b16 {%0,%1,%2,%3}, [%4];"
        : "=r"(r[0]), "=r"(r[1]), "=r"(r[2]), "=r"(r[3]) : "r"(addr));
}
__device__ __forceinline__ void mma_f16(float* c, const uint32_t* a, uint32_t b0, uint32_t b1) {
    asm volatile("mma.sync.aligned.m16n8k16.row.col.f32.f16.f16.f32 "
        "{%0,%1,%2,%3}, {%4,%5,%6,%7}, {%8,%9}, {%0,%1,%2,%3};"
        : "+f"(c[0]), "+f"(c[1]), "+f"(c[2]), "+f"(c[3])
        : "r"(a[0]), "r"(a[1]), "r"(a[2]), "r"(a[3]), "r"(b0), "r"(b1));
}
__device__ __forceinline__ uint32_t pack_f16x2(float lo, float hi) {
    uint32_t r;
    asm("cvt.rn.f16x2.f32 %0, %1, %2;" : "=r"(r) : "f"(hi), "f"(lo));
    return r;
}
__device__ __forceinline__ float sigf(float z) {
    return __fdividef(1.0f, 1.0f + __expf(-z));
}

__global__ void __launch_bounds__(NTHR, 3) attn_kernel(
    const float* __restrict__ seq, const float* __restrict__ tgt,
    const int* __restrict__ mask,
    const float* __restrict__ w1, const float* __restrict__ b1,
    const float* __restrict__ w2, const float* __restrict__ b2,
    float* __restrict__ out)
{
    extern __shared__ __align__(16) char smem[];
    const uint32_t sb = smem_u32(smem);
    const int b = blockIdx.x, tid = threadIdx.x, wid = tid >> 5, lid = tid & 31;
    const int tig = lid & 3, g = lid >> 2;

    float* sC = (float*)(smem + OFF_C);
    float* sP = (float*)(smem + OFF_P);
    float* sZ = (float*)(smem + OFF_Z);
    float* sM = (float*)(smem + OFF_M);
    float* sF = (float*)(smem + OFF_F);
    float* sR = (float*)(smem + OFF_R);
    float* sS = (float*)(smem + OFF_S);
    float* sW = (float*)(smem + OFF_WT);
    float* sPar = (float*)(smem + OFF_PAR);
    __half* Wh  = (__half*)(smem + OFF_WH);
    __half* Ahi = (__half*)(smem + OFF_AHI);
    __half* Alo = (__half*)(smem + OFF_ALO);
    float* fstage = (float*)(smem + OFF_AHI);   // fp32 staging, pitch 97 (37KB, fits in A planes)

    // ---- build Wh (fp16) + stage w2/tgt ----
    for (int i = tid; i < 96 * 96; i += NTHR) {
        int e = i / 96, d = i - e * 96;
        Wh[e * PW + d] = __float2half_rn(__ldg(w1 + i));
    }
    for (int i = tid; i < 96 * 96; i += NTHR) {
        int r = i / 96, c = i - r * 96;
        fstage[r * 97 + c] = __ldg(w2 + i);
    }
    if (tid >= 128 && tid < 224) sW[tid - 128] = __ldg(tgt + (size_t)b * 96 + (tid - 128));
    if (tid < 96) sP[tid] = 0.0f;
    if (tid == 0) { *sZ = 0.0f; *sM = -3.0e38f; }
    __syncthreads();

    // c[e] = b1[e] + b2[e] + tgt . w2[e,:]  (exact fp32)
    if (tid < 96) {
        float acc = __ldg(b1 + tid) + __ldg(b2 + tid);
        const float* wr = fstage + tid * 97;
        #pragma unroll 8
        for (int d = 0; d < 96; ++d) acc = fmaf(sW[d], wr[d], acc);
        sC[tid] = acc;
    }
    __syncthreads();

    // per-lane ldmatrix addresses: warp owns rows [wid*16, wid*16+16)
    const int m0 = wid * 16;
    const int rowA = m0 + (lid & 15);
    const int colA = (lid & 16) ? 8 : 0;
    const uint32_t aAhi = sb + OFF_AHI + (uint32_t)(rowA * PW + colA) * 2u;
    const uint32_t aAlo = sb + OFF_ALO + (uint32_t)(rowA * PW + colA) * 2u;
    const int eB = ((lid & 16) ? 8 : 0) + (lid & 7);
    const int dB = (lid & 8) ? 8 : 0;
    const uint32_t aWh = sb + OFF_WH + (uint32_t)(eB * PW + dB) * 2u;

    const size_t mrow = (size_t)b * (SEQ + 1);

    for (int t = 0; t < NTILE; ++t) {
        // ---- 1. load X tile, split hi/lo (fp16), store planes ----
        const float4* g4 = (const float4*)(seq + ((size_t)b * SEQ + (size_t)t * TM) * 96);
        #pragma unroll 12
        for (int i = tid; i < 3072; i += NTHR) {
            float4 v = g4[i];
            int e4 = i * 4;
            int r = e4 / 96, c = e4 - r * 96;
            __half hx = __float2half_rn(v.x), hy = __float2half_rn(v.y);
            __half hz = __float2half_rn(v.z), hw = __float2half_rn(v.w);
            uint32_t h01 = pack_f16x2(__half2float(hx), __half2float(hy));
            uint32_t h23 = pack_f16x2(__half2float(hz), __half2float(hw));
            uint32_t l01 = pack_f16x2(v.x - __half2float(hx), v.y - __half2float(hy));
            uint32_t l23 = pack_f16x2(v.z - __half2float(hz), v.w - __half2float(hw));
            uint32_t off = (uint32_t)(r * PW + c) * 2u;
            *(uint2*)(smem + OFF_AHI + off) = make_uint2(h01, h23);
            *(uint2*)(smem + OFF_ALO + off) = make_uint2(l01, l23);
        }
        __syncthreads();

        // ---- 2+3. HMMA (2-pass over N) + sigmoid-sum ----
        float slo = 0.0f, shi = 0.0f;
        #pragma unroll
        for (int p = 0; p < 2; ++p) {
            float acc[6][4];
            #pragma unroll
            for (int nt = 0; nt < 6; ++nt)
                #pragma unroll
                for (int q = 0; q < 4; ++q) acc[nt][q] = 0.0f;

            const uint32_t aWp = aWh + (uint32_t)(p * 48 * PW * 2);
            #pragma unroll
            for (int ks = 0; ks < 6; ++ks) {
                const uint32_t kb = (uint32_t)ks * 32u;
                uint32_t ah[4], al[4], bb[3][4];
                ldsm4(ah, aAhi + kb);
                ldsm4(al, aAlo + kb);
                #pragma unroll
                for (int i = 0; i < 3; ++i) ldsm4(bb[i], aWp + (uint32_t)i * (16u * PW * 2u) + kb);
                #pragma unroll
                for (int nt = 0; nt < 6; ++nt) {
                    const uint32_t* bp = bb[nt >> 1] + (nt & 1) * 2;
                    mma_f16(acc[nt], ah, bp[0], bp[1]);
                }
                #pragma unroll
                for (int nt = 0; nt < 6; ++nt) {
                    const uint32_t* bp = bb[nt >> 1] + (nt & 1) * 2;
                    mma_f16(acc[nt], al, bp[0], bp[1]);
                }
            }
            #pragma unroll
            for (int nt = 0; nt < 6; ++nt) {
                float c0 = sC[p * 48 + nt * 8 + tig * 2];
                float c1 = sC[p * 48 + nt * 8 + tig * 2 + 1];
                slo += sigf(acc[nt][0] + c0);
                slo += sigf(acc[nt][1] + c1);
                shi += sigf(acc[nt][2] + c0);
                shi += sigf(acc[nt][3] + c1);
            }
        }
        slo += __shfl_xor_sync(0xffffffffu, slo, 1);
        slo += __shfl_xor_sync(0xffffffffu, slo, 2);
        shi += __shfl_xor_sync(0xffffffffu, shi, 1);
        shi += __shfl_xor_sync(0xffffffffu, shi, 2);
        if (tig == 0) {
            sS[m0 + g]     = slo;
            sS[m0 + 8 + g] = shi;
        }
        __syncthreads();

        // ---- 4. online softmax (rows on warps 0-3) ----
        float score = 0.0f;
        if (tid < 128) {
            int mk = __ldg(mask + mrow + (size_t)t * TM + tid);
            score = mk ? -1.0e9f : sS[tid];
            float wmax = score;
            #pragma unroll
            for (int o = 16; o > 0; o >>= 1)
                wmax = fmaxf(wmax, __shfl_xor_sync(0xffffffffu, wmax, o));
            if (lid == 0) sR[wid] = wmax;
        }
        __syncthreads();
        if (tid == 0) {
            float tmax = fmaxf(fmaxf(sR[0], sR[1]), fmaxf(sR[2], sR[3]));
            float newM = fmaxf(*sM, tmax);
            *sF = __expf(*sM - newM);
            *sM = newM;
        }
        __syncthreads();
        if (tid < 128) {
            float wgt = __expf(score - *sM);
            sW[tid] = wgt;
            #pragma unroll
            for (int o = 16; o > 0; o >>= 1)
                wgt += __shfl_xor_sync(0xffffffffu, wgt, o);
            if (lid == 0) sR[wid] = wgt;
        }
        __syncthreads();
        if (tid == 0) *sZ = (*sZ) * (*sF) + (sR[0] + sR[1] + sR[2] + sR[3]);

        // ---- 5. weighted pooling of X (192 threads: 96 cols x 2 s-halves) ----
        if (tid < 192) {
            int col = (tid < 96) ? tid : tid - 96;
            int s0 = (tid < 96) ? 0 : 64;
            float pacc = 0.0f;
            const __half* xh = Ahi + col + s0 * PW;
            const __half* xl = Alo + col + s0 * PW;
            const float* wp = sW + s0;
            #pragma unroll 4
            for (int s = 0; s < 64; ++s)
                pacc = fmaf(wp[s], __half2float(xh[s * PW]) + __half2float(xl[s * PW]), pacc);
            sPar[tid] = pacc;
        }
        __syncthreads();
        if (tid < 96) sP[tid] = sP[tid] * (*sF) + sPar[tid] + sPar[tid + 96];
        __syncthreads();
    }

    // ---- epilogue: out[e] = b1[e] + (P/Z) . w1[e,:] (exact fp32) ----
    for (int i = tid; i < 96 * 96; i += NTHR) {
        int r = i / 96, c = i - r * 96;
        fstage[r * 97 + c] = __ldg(w1 + i);
    }
    __syncthreads();
    if (tid < 96) {
        float invZ = __fdividef(1.0f, *sZ);
        float acc = __ldg(b1 + tid);
        const float* wr = fstage + tid * 97;
        #pragma unroll 8
        for (int d = 0; d < 96; ++d) acc = fmaf(sP[d] * invZ, wr[d], acc);
        out[(size_t)b * 96 + tid] = acc;
    }
}

extern "C" void kernel_launch(void* const* d_in, const int* in_sizes, int n_in,
                              void* d_out, int out_size) {
    const float* seq = (const float*)d_in[0];
    const float* tgt = (const float*)d_in[1];
    const int* mask = (const int*)d_in[2];
    const float* w1 = (const float*)d_in[3];
    const float* b1 = (const float*)d_in[4];
    const float* w2 = (const float*)d_in[5];
    const float* b2 = (const float*)d_in[6];
    float* out = (float*)d_out;
    (void)in_sizes; (void)n_in; (void)out_size;

    cudaFuncSetAttribute(attn_kernel, cudaFuncAttributeMaxDynamicSharedMemorySize, SMEM_TOTAL);
    attn_kernel<<<BATCH, NTHR, SMEM_TOTAL>>>(seq, tgt, mask, w1, b1, w2, b2, out);
}

// round 15
// speedup vs baseline: 2.3326x; 1.1063x over previous
#include <cuda_runtime.h>
#include <cuda_fp16.h>
#include <cstdint>

#define BATCH 2048
#define SEQ   512
#define TM    128
#define NTILE 4
#define NTHR  256
#define PW    104   // fp16 pitch (208B rows -> conflict-free ldmatrix)

// ---- SMEM layout (bytes) ----
#define OFF_C    0                      // c[96] f32
#define OFF_P    384                    // P[96] f32
#define OFF_Z    768
#define OFF_M    772
#define OFF_F    776
#define OFF_R    800                    // (unused scratch, kept for layout stability)
#define OFF_S    816                    // scores[128] f32
#define OFF_WT   1328                   // softmax weights [128] f32
#define OFF_PAR  1840                   // pooling partials [192] f32
#define OFF_WH   2608                   // Wh 96xPW fp16 = 19968
#define OFF_AHI  (OFF_WH + 19968)       // 22576, Ahi 128xPW fp16 = 26624
#define OFF_ALO  (OFF_AHI + 26624)      // 49200
#define SMEM_TOTAL (OFF_ALO + 26624)    // 75824

__device__ __forceinline__ uint32_t smem_u32(const void* p) {
    uint32_t a;
    asm("{ .reg .u64 t; cvta.to.shared.u64 t, %1; cvt.u32.u64 %0, t; }" : "=r"(a) : "l"(p));
    return a;
}
__device__ __forceinline__ void ldsm4(uint32_t* r, uint32_t addr) {
    asm volatile("ldmatrix.sync.aligned.m8n8.x4.shared.b16 {%0,%1,%2,%3}, [%4];"
        : "=r"(r[0]), "=r"(r[1]), "=r"(r[2]), "=r"(r[3]) : "r"(addr));
}
__device__ __forceinline__ void mma_f16(float* c, const uint32_t* a, uint32_t b0, uint32_t b1) {
    asm volatile("mma.sync.aligned.m16n8k16.row.col.f32.f16.f16.f32 "
        "{%0,%1,%2,%3}, {%4,%5,%6,%7}, {%8,%9}, {%0,%1,%2,%3};"
        : "+f"(c[0]), "+f"(c[1]), "+f"(c[2]), "+f"(c[3])
        : "r"(a[0]), "r"(a[1]), "r"(a[2]), "r"(a[3]), "r"(b0), "r"(b1));
}
__device__ __forceinline__ uint32_t pack_f16x2(float lo, float hi) {
    uint32_t r;
    asm("cvt.rn.f16x2.f32 %0, %1, %2;" : "=r"(r) : "f"(hi), "f"(lo));
    return r;
}
__device__ __forceinline__ float sigf(float z) {
    return __fdividef(1.0f, 1.0f + __expf(-z));
}

__global__ void __launch_bounds__(NTHR, 3) attn_kernel(
    const float* __restrict__ seq, const float* __restrict__ tgt,
    const int* __restrict__ mask,
    const float* __restrict__ w1, const float* __restrict__ b1,
    const float* __restrict__ w2, const float* __restrict__ b2,
    float* __restrict__ out)
{
    extern __shared__ __align__(16) char smem[];
    const uint32_t sb = smem_u32(smem);
    const int b = blockIdx.x, tid = threadIdx.x, wid = tid >> 5, lid = tid & 31;
    const int tig = lid & 3, g = lid >> 2;

    float* sC = (float*)(smem + OFF_C);
    float* sP = (float*)(smem + OFF_P);
    float* sZ = (float*)(smem + OFF_Z);
    float* sM = (float*)(smem + OFF_M);
    float* sF = (float*)(smem + OFF_F);
    float* sS = (float*)(smem + OFF_S);
    float* sW = (float*)(smem + OFF_WT);
    float* sPar = (float*)(smem + OFF_PAR);
    __half* Wh  = (__half*)(smem + OFF_WH);
    __half* Ahi = (__half*)(smem + OFF_AHI);
    __half* Alo = (__half*)(smem + OFF_ALO);
    float* fstage = (float*)(smem + OFF_AHI);   // fp32 staging, pitch 97 (37KB, fits in A planes)

    // ---- build Wh (fp16) + stage w2/tgt ----
    for (int i = tid; i < 96 * 96; i += NTHR) {
        int e = i / 96, d = i - e * 96;
        Wh[e * PW + d] = __float2half_rn(__ldg(w1 + i));
    }
    for (int i = tid; i < 96 * 96; i += NTHR) {
        int r = i / 96, c = i - r * 96;
        fstage[r * 97 + c] = __ldg(w2 + i);
    }
    if (tid >= 128 && tid < 224) sW[tid - 128] = __ldg(tgt + (size_t)b * 96 + (tid - 128));
    if (tid < 96) sP[tid] = 0.0f;
    if (tid == 0) { *sZ = 0.0f; *sM = -3.0e38f; }
    __syncthreads();

    // c[e] = b1[e] + b2[e] + tgt . w2[e,:]  (exact fp32)
    if (tid < 96) {
        float acc = __ldg(b1 + tid) + __ldg(b2 + tid);
        const float* wr = fstage + tid * 97;
        #pragma unroll 8
        for (int d = 0; d < 96; ++d) acc = fmaf(sW[d], wr[d], acc);
        sC[tid] = acc;
    }
    __syncthreads();

    // per-lane ldmatrix addresses: warp owns rows [wid*16, wid*16+16)
    const int m0 = wid * 16;
    const int rowA = m0 + (lid & 15);
    const int colA = (lid & 16) ? 8 : 0;
    const uint32_t aAhi = sb + OFF_AHI + (uint32_t)(rowA * PW + colA) * 2u;
    const int eB = ((lid & 16) ? 8 : 0) + (lid & 7);
    const int dB = (lid & 8) ? 8 : 0;
    const uint32_t aWh = sb + OFF_WH + (uint32_t)(eB * PW + dB) * 2u;

    const size_t mrow = (size_t)b * (SEQ + 1);

    for (int t = 0; t < NTILE; ++t) {
        // ---- 1. load X tile, split hi/lo (fp16), store planes ----
        const float4* g4 = (const float4*)(seq + ((size_t)b * SEQ + (size_t)t * TM) * 96);
        #pragma unroll 12
        for (int i = tid; i < 3072; i += NTHR) {
            float4 v = g4[i];
            int e4 = i * 4;
            int r = e4 / 96, c = e4 - r * 96;
            __half hx = __float2half_rn(v.x), hy = __float2half_rn(v.y);
            __half hz = __float2half_rn(v.z), hw = __float2half_rn(v.w);
            uint32_t h01 = pack_f16x2(__half2float(hx), __half2float(hy));
            uint32_t h23 = pack_f16x2(__half2float(hz), __half2float(hw));
            uint32_t l01 = pack_f16x2(v.x - __half2float(hx), v.y - __half2float(hy));
            uint32_t l23 = pack_f16x2(v.z - __half2float(hz), v.w - __half2float(hw));
            uint32_t off = (uint32_t)(r * PW + c) * 2u;
            *(uint2*)(smem + OFF_AHI + off) = make_uint2(h01, h23);
            *(uint2*)(smem + OFF_ALO + off) = make_uint2(l01, l23);
        }
        // hoist mask loads (warp 0 only) — resolve under the MMA phase
        int mk[4];
        if (wid == 0) {
            #pragma unroll
            for (int j = 0; j < 4; ++j)
                mk[j] = __ldg(mask + mrow + (size_t)t * TM + lid + 32 * j);
        }
        __syncthreads();

        // ---- 2+3. HMMA (2-pass over N, hi-plane only) + sigmoid-sum ----
        float slo = 0.0f, shi = 0.0f;
        #pragma unroll
        for (int p = 0; p < 2; ++p) {
            float acc[6][4];
            #pragma unroll
            for (int nt = 0; nt < 6; ++nt)
                #pragma unroll
                for (int q = 0; q < 4; ++q) acc[nt][q] = 0.0f;

            const uint32_t aWp = aWh + (uint32_t)(p * 48 * PW * 2);
            #pragma unroll
            for (int ks = 0; ks < 6; ++ks) {
                const uint32_t kb = (uint32_t)ks * 32u;
                uint32_t ah[4], bb[3][4];
                ldsm4(ah, aAhi + kb);
                #pragma unroll
                for (int i = 0; i < 3; ++i) ldsm4(bb[i], aWp + (uint32_t)i * (16u * PW * 2u) + kb);
                #pragma unroll
                for (int nt = 0; nt < 6; ++nt) {
                    const uint32_t* bp = bb[nt >> 1] + (nt & 1) * 2;
                    mma_f16(acc[nt], ah, bp[0], bp[1]);
                }
            }
            #pragma unroll
            for (int nt = 0; nt < 6; ++nt) {
                float c0 = sC[p * 48 + nt * 8 + tig * 2];
                float c1 = sC[p * 48 + nt * 8 + tig * 2 + 1];
                slo += sigf(acc[nt][0] + c0);
                slo += sigf(acc[nt][1] + c1);
                shi += sigf(acc[nt][2] + c0);
                shi += sigf(acc[nt][3] + c1);
            }
        }
        slo += __shfl_xor_sync(0xffffffffu, slo, 1);
        slo += __shfl_xor_sync(0xffffffffu, slo, 2);
        shi += __shfl_xor_sync(0xffffffffu, shi, 1);
        shi += __shfl_xor_sync(0xffffffffu, shi, 2);
        if (tig == 0) {
            sS[m0 + g]     = slo;
            sS[m0 + 8 + g] = shi;
        }
        __syncthreads();

        // ---- 4. online softmax: single warp (4 rows/lane) ----
        if (wid == 0) {
            float sc[4];
            #pragma unroll
            for (int j = 0; j < 4; ++j)
                sc[j] = mk[j] ? -1.0e9f : sS[lid + 32 * j];
            float mx = fmaxf(fmaxf(sc[0], sc[1]), fmaxf(sc[2], sc[3]));
            #pragma unroll
            for (int o = 16; o > 0; o >>= 1)
                mx = fmaxf(mx, __shfl_xor_sync(0xffffffffu, mx, o));
            float oldM = *sM;
            float newM = fmaxf(oldM, mx);
            float F = __expf(oldM - newM);
            float ssum = 0.0f;
            #pragma unroll
            for (int j = 0; j < 4; ++j) {
                float w = __expf(sc[j] - newM);
                sW[lid + 32 * j] = w;
                ssum += w;
            }
            #pragma unroll
            for (int o = 16; o > 0; o >>= 1)
                ssum += __shfl_xor_sync(0xffffffffu, ssum, o);
            if (lid == 0) {
                *sZ = (*sZ) * F + ssum;
                *sM = newM;
                *sF = F;
            }
        }
        __syncthreads();

        // ---- 5. weighted pooling: 96 threads x 2 cols (half2), 2 s-halves ----
        if (tid < 96) {
            int p = tid & 47;        // col pair
            int h = tid >> 6;        // 0 for tid<64? no: use explicit split
            // remap: threads 0..47 -> half 0, 48..95 -> half 1
            p = (tid < 48) ? tid : tid - 48;
            h = (tid < 48) ? 0 : 1;
            int s0 = h * 64;
            float a0 = 0.0f, a1 = 0.0f;
            const uint32_t* xh = (const uint32_t*)(Ahi + s0 * PW + 2 * p);
            const uint32_t* xl = (const uint32_t*)(Alo + s0 * PW + 2 * p);
            const float* wp = sW + s0;
            #pragma unroll 4
            for (int s = 0; s < 64; ++s) {
                uint32_t uh = xh[s * (PW / 2)];
                uint32_t ul = xl[s * (PW / 2)];
                float2 fh = __half22float2(*(const __half2*)&uh);
                float2 fl = __half22float2(*(const __half2*)&ul);
                float w = wp[s];
                a0 = fmaf(w, fh.x + fl.x, a0);
                a1 = fmaf(w, fh.y + fl.y, a1);
            }
            sPar[h * 96 + 2 * p]     = a0;
            sPar[h * 96 + 2 * p + 1] = a1;
        }
        __syncthreads();
        if (tid < 96) sP[tid] = sP[tid] * (*sF) + sPar[tid] + sPar[96 + tid];
        __syncthreads();
    }

    // ---- epilogue: out[e] = b1[e] + (P/Z) . w1[e,:] (exact fp32) ----
    for (int i = tid; i < 96 * 96; i += NTHR) {
        int r = i / 96, c = i - r * 96;
        fstage[r * 97 + c] = __ldg(w1 + i);
    }
    __syncthreads();
    if (tid < 96) {
        float invZ = __fdividef(1.0f, *sZ);
        float acc = __ldg(b1 + tid);
        const float* wr = fstage + tid * 97;
        #pragma unroll 8
        for (int d = 0; d < 96; ++d) acc = fmaf(sP[d] * invZ, wr[d], acc);
        out[(size_t)b * 96 + tid] = acc;
    }
}

extern "C" void kernel_launch(void* const* d_in, const int* in_sizes, int n_in,
                              void* d_out, int out_size) {
    const float* seq = (const float*)d_in[0];
    const float* tgt = (const float*)d_in[1];
    const int* mask = (const int*)d_in[2];
    const float* w1 = (const float*)d_in[3];
    const float* b1 = (const float*)d_in[4];
    const float* w2 = (const float*)d_in[5];
    const float* b2 = (const float*)d_in[6];
    float* out = (float*)d_out;
    (void)in_sizes; (void)n_in; (void)out_size;

    cudaFuncSetAttribute(attn_kernel, cudaFuncAttributeMaxDynamicSharedMemorySize, SMEM_TOTAL);
    attn_kernel<<<BATCH, NTHR, SMEM_TOTAL>>>(seq, tgt, mask, w1, b1, w2, b2, out);
}